// round 4
// baseline (speedup 1.0000x reference)
#include <cuda_runtime.h>

// TwoTowerModel: B=524288, EMB=64, tower [128,64], fp32.
// out[b] = cos( relu-MLP(user_table[user_ids[b]]), relu-MLP(item_table[item_ids[b]]) )
//
// Design (sm_103a):
//  - 1 block = 128 rows, 256 threads, 1 CTA/SM (193 KB smem).
//  - Embeddings gathered into transposed smem Xt[k][row] (conflict-free STS:
//    warp lanes write 32 consecutive rows at fixed k).
//  - GEMMs: 8x8 (layer1) / 8x4 (layer2) register tiles, accumulators packed as
//    row-pairs in 64-bit regs and driven by fma.rn.f32x2 (FFMA2) -- 2 MACs per
//    issue slot vs rt=2 scalar FFMA. A-operands come pre-packed from LDS.128;
//    only B-operands need a dup mov.b64 {f,f}.
//  - H stored transposed Ht[c][row] so layer2 reuses the same access pattern.
//  - User vec parked in smem while item tower reuses all buffers; final
//    per-row L2-normalize + dot.

#define NTHREADS 256
#define TILE 128

// shared layout (floats):
//  sW1 8192 | sW2 8192 | sB1 128 | sB2 64 | sXt 8192 | sHt 16384 | sU 8192
#define SMEM_FLOATS (8192 + 8192 + 128 + 64 + 8192 + 16384 + 8192)

__device__ __forceinline__ unsigned long long dup2(float x) {
    unsigned long long r;
    asm("mov.b64 %0, {%1, %1};" : "=l"(r) : "f"(x));
    return r;
}

__device__ __forceinline__ void fma2(unsigned long long& d,
                                     unsigned long long a,
                                     unsigned long long b) {
    asm("fma.rn.f32x2 %0, %1, %2, %0;" : "+l"(d) : "l"(a), "l"(b));
}

__device__ __forceinline__ float2 unpk(unsigned long long v) {
    float2 f;
    asm("mov.b64 {%0, %1}, %2;" : "=f"(f.x), "=f"(f.y) : "l"(v));
    return f;
}

__global__ void __launch_bounds__(NTHREADS, 1)
tt_kernel(const int* __restrict__ user_ids, const int* __restrict__ item_ids,
          const float4* __restrict__ user_tab, const float4* __restrict__ item_tab,
          const float* __restrict__ uW1, const float* __restrict__ ub1,
          const float* __restrict__ uW2, const float* __restrict__ ub2,
          const float* __restrict__ iW1, const float* __restrict__ ib1,
          const float* __restrict__ iW2, const float* __restrict__ ib2,
          float* __restrict__ out, int B)
{
    extern __shared__ float sm[];
    float* sW1 = sm;                 // [64][128]  k-major
    float* sW2 = sW1 + 8192;         // [128][64]  k-major
    float* sB1 = sW2 + 8192;         // [128]
    float* sB2 = sB1 + 128;          // [64]
    float* sXt = sB2 + 64;           // [64][128]  Xt[k][row]   (reused: item vec)
    float* sHt = sXt + 8192;         // [128][128] Ht[c][row]
    float* sU  = sHt + 16384;        // [64][128]  user vecT[c][row]

    const int tid = threadIdx.x;
    const int tx = tid & 15;         // row group: rows 8*tx .. 8*tx+7
    const int ty = tid >> 4;         // col group
    const int base = blockIdx.x * TILE;

    for (int tower = 0; tower < 2; ++tower) {
        const int*    ids = tower ? item_ids : user_ids;
        const float4* tab = tower ? item_tab : user_tab;
        const float*  W1  = tower ? iW1 : uW1;
        const float*  B1  = tower ? ib1 : ub1;
        const float*  W2  = tower ? iW2 : uW2;
        const float*  B2  = tower ? ib2 : ub2;
        float*       vecT = tower ? sXt : sU;   // layer-2 output [64][128]

        if (tower) __syncthreads();  // protect sW1/sW2/sXt reuse across phases

        // ---- stage weights into smem ----
        {
            const float4* s1 = (const float4*)W1;
            float4*       d1 = (float4*)sW1;
            #pragma unroll
            for (int i = 0; i < 8; ++i) d1[tid + i * 256] = s1[tid + i * 256];
            const float4* s2 = (const float4*)W2;
            float4*       d2 = (float4*)sW2;
            #pragma unroll
            for (int i = 0; i < 8; ++i) d2[tid + i * 256] = s2[tid + i * 256];
            if (tid < 128)      sB1[tid] = B1[tid];
            else if (tid < 192) sB2[tid - 128] = B2[tid - 128];
        }

        // ---- gather embeddings -> Xt[k][row] (transposed) ----
        {
            const int row = tid & 127;
            const int h   = tid >> 7;            // 0/1: low/high half of emb
            const int r   = base + row;
            const int id  = (r < B) ? ids[r] : 0;
            const float4* src = tab + (size_t)id * 16 + h * 8;
            #pragma unroll
            for (int s = 0; s < 8; ++s) {
                float4 v = src[s];
                const int k0 = (h * 8 + s) * 4;
                sXt[(k0 + 0) * 128 + row] = v.x;   // lanes = consecutive rows:
                sXt[(k0 + 1) * 128 + row] = v.y;   // conflict-free STS
                sXt[(k0 + 2) * 128 + row] = v.z;
                sXt[(k0 + 3) * 128 + row] = v.w;
            }
        }
        __syncthreads();

        // ---- layer 1: H[128r][128c] = relu(X @ W1 + b1), stored Ht[c][r] ----
        unsigned long long acc1[4][8];   // 4 row-pairs x 8 cols
        #pragma unroll
        for (int p = 0; p < 4; ++p)
            #pragma unroll
            for (int j = 0; j < 8; ++j) acc1[p][j] = 0ull;

        {
            const float* xa = sXt + 8 * tx;
            const float* wb = sW1 + 8 * ty;
            #pragma unroll 8
            for (int k = 0; k < 64; ++k) {
                const ulonglong2 A0 = *(const ulonglong2*)(xa + k * 128);
                const ulonglong2 A1 = *(const ulonglong2*)(xa + k * 128 + 4);
                const float4 b0 = *(const float4*)(wb + k * 128);
                const float4 b1 = *(const float4*)(wb + k * 128 + 4);
                unsigned long long a[4] = {A0.x, A0.y, A1.x, A1.y};
                unsigned long long bd[8] = {dup2(b0.x), dup2(b0.y), dup2(b0.z), dup2(b0.w),
                                            dup2(b1.x), dup2(b1.y), dup2(b1.z), dup2(b1.w)};
                #pragma unroll
                for (int p = 0; p < 4; ++p)
                    #pragma unroll
                    for (int j = 0; j < 8; ++j)
                        fma2(acc1[p][j], a[p], bd[j]);
            }
        }

        // epilogue: relu(+bias) -> Ht[c][row], float4 stores (conflict-free)
        #pragma unroll
        for (int j = 0; j < 8; ++j) {
            const int c = 8 * ty + j;
            const float bias = sB1[c];
            const float2 f0 = unpk(acc1[0][j]);
            const float2 f1 = unpk(acc1[1][j]);
            const float2 f2 = unpk(acc1[2][j]);
            const float2 f3 = unpk(acc1[3][j]);
            float4 v0 = make_float4(fmaxf(f0.x + bias, 0.f), fmaxf(f0.y + bias, 0.f),
                                    fmaxf(f1.x + bias, 0.f), fmaxf(f1.y + bias, 0.f));
            float4 v1 = make_float4(fmaxf(f2.x + bias, 0.f), fmaxf(f2.y + bias, 0.f),
                                    fmaxf(f3.x + bias, 0.f), fmaxf(f3.y + bias, 0.f));
            *(float4*)(sHt + c * 128 + 8 * tx)     = v0;
            *(float4*)(sHt + c * 128 + 8 * tx + 4) = v1;
        }
        __syncthreads();

        // ---- layer 2: O[128r][64c] = relu(H @ W2 + b2), stored vecT[c][r] ----
        unsigned long long acc2[4][4];   // 4 row-pairs x 4 cols
        #pragma unroll
        for (int p = 0; p < 4; ++p)
            #pragma unroll
            for (int j = 0; j < 4; ++j) acc2[p][j] = 0ull;

        {
            const float* ha  = sHt + 8 * tx;
            const float* wb2 = sW2 + 4 * ty;
            #pragma unroll 8
            for (int k = 0; k < 128; ++k) {
                const ulonglong2 A0 = *(const ulonglong2*)(ha + k * 128);
                const ulonglong2 A1 = *(const ulonglong2*)(ha + k * 128 + 4);
                const float4 b = *(const float4*)(wb2 + k * 64);
                unsigned long long a[4]  = {A0.x, A0.y, A1.x, A1.y};
                unsigned long long bd[4] = {dup2(b.x), dup2(b.y), dup2(b.z), dup2(b.w)};
                #pragma unroll
                for (int p = 0; p < 4; ++p)
                    #pragma unroll
                    for (int j = 0; j < 4; ++j)
                        fma2(acc2[p][j], a[p], bd[j]);
            }
        }

        #pragma unroll
        for (int j = 0; j < 4; ++j) {
            const int c = 4 * ty + j;
            const float bias = sB2[c];
            const float2 f0 = unpk(acc2[0][j]);
            const float2 f1 = unpk(acc2[1][j]);
            const float2 f2 = unpk(acc2[2][j]);
            const float2 f3 = unpk(acc2[3][j]);
            float4 v0 = make_float4(fmaxf(f0.x + bias, 0.f), fmaxf(f0.y + bias, 0.f),
                                    fmaxf(f1.x + bias, 0.f), fmaxf(f1.y + bias, 0.f));
            float4 v1 = make_float4(fmaxf(f2.x + bias, 0.f), fmaxf(f2.y + bias, 0.f),
                                    fmaxf(f3.x + bias, 0.f), fmaxf(f3.y + bias, 0.f));
            *(float4*)(vecT + c * 128 + 8 * tx)     = v0;
            *(float4*)(vecT + c * 128 + 8 * tx + 4) = v1;
        }
    }
    __syncthreads();

    // ---- normalize + dot ----
    if (tid < TILE) {
        const int r = base + tid;
        if (r < B) {
            float su = 0.f, si = 0.f, d = 0.f;
            #pragma unroll 8
            for (int c = 0; c < 64; ++c) {
                const float u = sU[c * 128 + tid];
                const float v = sXt[c * 128 + tid];
                su = fmaf(u, u, su);
                si = fmaf(v, v, si);
                d  = fmaf(u, v, d);
            }
            const float nu = fmaxf(sqrtf(su), 1e-12f);
            const float ni = fmaxf(sqrtf(si), 1e-12f);
            out[r] = d / (nu * ni);
        }
    }
}

extern "C" void kernel_launch(void* const* d_in, const int* in_sizes, int n_in,
                              void* d_out, int out_size)
{
    const int*    user_ids = (const int*)d_in[0];
    const int*    item_ids = (const int*)d_in[1];
    const float4* utab     = (const float4*)d_in[2];
    const float4* itab     = (const float4*)d_in[3];
    const float*  uW1 = (const float*)d_in[4];
    const float*  ub1 = (const float*)d_in[5];
    const float*  uW2 = (const float*)d_in[6];
    const float*  ub2 = (const float*)d_in[7];
    const float*  iW1 = (const float*)d_in[8];
    const float*  ib1 = (const float*)d_in[9];
    const float*  iW2 = (const float*)d_in[10];
    const float*  ib2 = (const float*)d_in[11];
    float* out = (float*)d_out;

    const int B = in_sizes[0];
    const int smem_bytes = SMEM_FLOATS * (int)sizeof(float);  // 197376

    static int attr_done = 0;
    // idempotent + deterministic: set every launch (cheap, not a stream op)
    (void)attr_done;
    cudaFuncSetAttribute(tt_kernel, cudaFuncAttributeMaxDynamicSharedMemorySize,
                         smem_bytes);

    const int grid = (B + TILE - 1) / TILE;
    tt_kernel<<<grid, NTHREADS, smem_bytes>>>(
        user_ids, item_ids, utab, itab,
        uW1, ub1, uW2, ub2, iW1, ib1, iW2, ib2,
        out, B);
}